// round 6
// baseline (speedup 1.0000x reference)
#include <cuda_runtime.h>
#include <cstdint>

// ============================================================
// W8A8 linear: out[M,N] = xs * (Xq[M,K] @ Wq[N,K]^T) * wsc[n] + bias[n]
//   M = 8192, N = 4096, K = 4096
// Base-sm_103 (compute_103 virtual arch; no tcgen05).
// Round 6: int8 operands in smem, widened to fp16 in registers
// (PRMT + sub.f16x2 magic, exact), mma.m16n8k16.f16 HMMA.
// 16 warps (4/SMSP) for latency hiding; crossbar traffic halved;
// persistent CTAs; 8-stage cp.async ring.
// Data stored k-PERMUTED so one ldmatrix.x4 (as b16) yields two
// exact k16 fp16 fragments after widening.
// ============================================================

#define MM 8192
#define NN 4096
#define KK 4096

#define BM 128
#define BN 256
#define BK 64                 // s8 elements; 64 bytes per row
#define STAGES 8
#define KITERS (KK / BK)      // 64
#define NTHREADS 512          // 16 warps
#define TILES_X (NN / BN)     // 16
#define NTILES ((MM / BM) * (NN / BN))   // 1024

// ---- device scratch: quantized, biased (+128), k-permuted u8 ----
__device__ __align__(128) uint8_t g_xq[(size_t)MM * KK];
__device__ __align__(128) uint8_t g_wq[(size_t)NN * KK];

// ============================================================
// PTX helpers (base-arch only)
// ============================================================
__device__ __forceinline__ uint32_t smem_to_u32(const void* p) {
    uint32_t a;
    asm("{ .reg .u64 t; cvta.to.shared.u64 t, %1; cvt.u32.u64 %0, t; }"
        : "=r"(a) : "l"(p));
    return a;
}

__device__ __forceinline__ void cp_async16(uint32_t dst, const void* src) {
    asm volatile("cp.async.cg.shared.global [%0], [%1], 16;"
                 :: "r"(dst), "l"(src) : "memory");
}
#define CP_COMMIT() asm volatile("cp.async.commit_group;" ::: "memory")
#define CP_WAIT(n)  asm volatile("cp.async.wait_group %0;" :: "n"(n) : "memory")

#define LDMATRIX_X4(r, addr) \
    asm volatile("ldmatrix.sync.aligned.m8n8.x4.shared.b16 {%0,%1,%2,%3}, [%4];" \
                 : "=r"((r)[0]), "=r"((r)[1]), "=r"((r)[2]), "=r"((r)[3]) \
                 : "r"(addr))

__device__ __forceinline__ uint32_t prmt(uint32_t a, uint32_t b, uint32_t sel) {
    uint32_t d;
    asm("prmt.b32 %0, %1, %2, %3;" : "=r"(d) : "r"(a), "r"(b), "r"(sel));
    return d;
}
__device__ __forceinline__ uint32_t hsub2(uint32_t a, uint32_t b) {
    uint32_t d;
    asm("sub.rn.f16x2 %0, %1, %2;" : "=r"(d) : "r"(a), "r"(b));
    return d;
}

// widen 4 biased-u8 (elements {2q,2q+1,2q+8,2q+9}) -> two fp16x2 regs
// fp16 magic: 0x64 high byte => 1024+u ; subtract 1152 => exact s8 value
#define U8MAGIC 0x64646464u
#define U8BIAS  0x64806480u   // fp16x2 (1152, 1152)
__device__ __forceinline__ void cvt_u8(uint32_t r, uint32_t& lo, uint32_t& hi) {
    lo = hsub2(prmt(r, U8MAGIC, 0x5140), U8BIAS);
    hi = hsub2(prmt(r, U8MAGIC, 0x5342), U8BIAS);
}

// D(16x8 f32) += A(16x16 f16) * B(16x8 f16)
__device__ __forceinline__ void mma_f16(float* d, const uint32_t* a,
                                        uint32_t b0, uint32_t b1) {
    asm volatile(
        "mma.sync.aligned.m16n8k16.row.col.f32.f16.f16.f32 "
        "{%0,%1,%2,%3}, {%4,%5,%6,%7}, {%8,%9}, {%0,%1,%2,%3};"
        : "+f"(d[0]), "+f"(d[1]), "+f"(d[2]), "+f"(d[3])
        : "r"(a[0]), "r"(a[1]), "r"(a[2]), "r"(a[3]),
          "r"(b0), "r"(b1));
}

// ============================================================
// Quantization pre-pass: f32 -> biased u8, k-PERMUTED.
// Per 32-element k-block, output position 4w+s holds element
//   16*(w>>2) + [2q, 2q+1, 2q+8, 2q+9][s]   where q = w&3.
// Built from natural words with one PRMT per output word.
// ============================================================
__global__ void quantize_kernel(const float4* __restrict__ x4,
                                const float4* __restrict__ w4,
                                const float* __restrict__ xs_ptr,
                                int n32x, int n32tot) {
    int i = blockIdx.x * blockDim.x + threadIdx.x;
    if (i >= n32tot) return;

    const float4* src;
    uint8_t* dst;
    float inv;
    if (i < n32x) {
        inv = 1.0f / __ldg(xs_ptr);
        src = x4 + (size_t)i * 8;
        dst = g_xq + (size_t)i * 32;
    } else {
        int j = i - n32x;
        inv = 1.0f;
        src = w4 + (size_t)j * 8;
        dst = g_wq + (size_t)j * 32;
    }

    uint32_t nat[8];
    #pragma unroll
    for (int w = 0; w < 8; w++) {
        float4 v = src[w];
        int a = (int)fminf(127.f, fmaxf(-128.f, rintf(v.x * inv))) + 128;
        int b = (int)fminf(127.f, fmaxf(-128.f, rintf(v.y * inv))) + 128;
        int c = (int)fminf(127.f, fmaxf(-128.f, rintf(v.z * inv))) + 128;
        int d = (int)fminf(127.f, fmaxf(-128.f, rintf(v.w * inv))) + 128;
        nat[w] = (uint32_t)a | ((uint32_t)b << 8) |
                 ((uint32_t)c << 16) | ((uint32_t)d << 24);
    }

    uint32_t out[8];
    #pragma unroll
    for (int w = 0; w < 8; w++) {
        int h = w >> 2, q = w & 3;
        uint32_t a = nat[4 * h + (q >> 1)];
        uint32_t b = nat[4 * h + 2 + (q >> 1)];
        out[w] = prmt(a, b, (q & 1) ? 0x7632u : 0x5410u);
    }
    uint4* d4 = reinterpret_cast<uint4*>(dst);
    d4[0] = make_uint4(out[0], out[1], out[2], out[3]);
    d4[1] = make_uint4(out[4], out[5], out[6], out[7]);
}

// ============================================================
// GEMM kernel: persistent CTAs, 8-stage cp.async ring, s8 smem.
//   512 threads = 16 warps, warp grid 4(m) x 4(n), warp tile 32x64.
//   Stage: A 128 rows x 64B, B 256 rows x 64B  (24 KB).
//   Swizzle (64B rows): chunk' = chunk ^ ((row>>1)&3)  -> LDSM
//   conflict-free (8 rows hit 8 distinct 16B slots per 128B).
// ============================================================
#define SOFF_SC   0
#define SOFF_BI   1024
#define SOFF_ST   2048
#define STAGE_BYTES ((BM + BN) * BK)         // 24576
#define ASTAGE(s) (SOFF_ST + (s) * STAGE_BYTES)
#define BSTAGE(s) (ASTAGE(s) + BM * BK)
#define SMEM_TOTAL (SOFF_ST + STAGES * STAGE_BYTES)   // 198656

__device__ __forceinline__ void load_stage(uint32_t sb, int s, int kiter,
                                           int m0, int n0, int tid) {
    int k0 = kiter * BK;
    const uint8_t* Ab = g_xq + (size_t)m0 * KK + k0;
    const uint8_t* Bb = g_wq + (size_t)n0 * KK + k0;
    #pragma unroll
    for (int i = 0; i < (BM + BN) * 4 / NTHREADS; i++) {   // 3
        int idx = tid + i * NTHREADS;
        int row = idx >> 2;
        int c = idx & 3;                                   // 16B chunk
        if (row < BM) {
            cp_async16(sb + ASTAGE(s) + row * 64 + ((c ^ ((row >> 1) & 3)) << 4),
                       Ab + (size_t)row * KK + c * 16);
        } else {
            int br = row - BM;
            cp_async16(sb + BSTAGE(s) + br * 64 + ((c ^ ((br >> 1) & 3)) << 4),
                       Bb + (size_t)br * KK + c * 16);
        }
    }
}

__global__ void __launch_bounds__(NTHREADS, 1)
w8a8_gemm_kernel(float* __restrict__ out,
                 const float* __restrict__ wsc,
                 const float* __restrict__ bias,
                 const float* __restrict__ xs_ptr) {
    extern __shared__ char smem[];
    uint32_t sb = smem_to_u32(smem);
    int tid  = threadIdx.x;
    int wid  = tid >> 5;
    int lane = tid & 31;
    int warp_m = wid & 3;     // m offset warp_m*32
    int warp_n = wid >> 2;    // n offset warp_n*64
    int G = gridDim.x;

    // ldmatrix lane addressing: 4 address groups of 8 lanes
    //  group 0: tile rows 0-7, chunk +0   -> reg0 (j0, low rows)
    //  group 1: rows 8-15, chunk +0       -> reg1 (j0, high rows)
    //  group 2: rows 0-7, chunk +1        -> reg2 (j1, low rows)
    //  group 3: rows 8-15, chunk +1       -> reg3 (j1, high rows)
    int rowin = ((lane >> 3) & 1) * 8 + (lane & 7);
    int csel  = lane >> 4;    // 0 or 1 (chunk select within k32 half)

    // ---- load cursor: continuous across this CTA's tile list ----
    int ltile = blockIdx.x;
    int lkit  = 0;
    int ls    = 0;

    // ---- stage sc/bias for first tile ----
    {
        int n0 = (blockIdx.x % TILES_X) * BN;
        for (int c = tid; c < BN; c += NTHREADS) {
            reinterpret_cast<float*>(smem + SOFF_SC)[c] = wsc[n0 + c];
            reinterpret_cast<float*>(smem + SOFF_BI)[c] = bias[n0 + c];
        }
    }

    // prologue: fill 7 of 8 stages
    #pragma unroll
    for (int p = 0; p < STAGES - 1; p++) {
        if (ltile < NTILES) {
            int lm0 = (ltile / TILES_X) * BM;
            int ln0 = (ltile % TILES_X) * BN;
            load_stage(sb, ls, lkit, lm0, ln0, tid);
            ls = (ls + 1) & (STAGES - 1);
            if (++lkit == KITERS) { lkit = 0; ltile += G; }
        }
        CP_COMMIT();
    }

    float xs = __ldg(xs_ptr);
    int cs = 0;   // compute stage

    for (int mytile = blockIdx.x; mytile < NTILES; mytile += G) {
        int m0 = (mytile / TILES_X) * BM;
        int n0 = (mytile % TILES_X) * BN;

        float acc[2][8][4] = {};   // [m16 tile][n8 tile][frag]

        for (int kit = 0; kit < KITERS; kit++) {
            CP_WAIT(STAGES - 2);
            __syncthreads();

            if (ltile < NTILES) {
                int lm0 = (ltile / TILES_X) * BM;
                int ln0 = (ltile % TILES_X) * BN;
                load_stage(sb, ls, lkit, lm0, ln0, tid);
                ls = (ls + 1) & (STAGES - 1);
                if (++lkit == KITERS) { lkit = 0; ltile += G; }
            }
            CP_COMMIT();

            uint32_t As = sb + ASTAGE(cs);
            uint32_t Bs = sb + BSTAGE(cs);
            cs = (cs + 1) & (STAGES - 1);

            #pragma unroll
            for (int h = 0; h < 2; h++) {        // k32 halves of the k64 slab
                int chunk = 2 * h + csel;
                uint32_t ra[2][4], rb[4][4];
                #pragma unroll
                for (int t = 0; t < 2; t++) {
                    int row = warp_m * 32 + t * 16 + rowin;
                    LDMATRIX_X4(ra[t], As + row * 64 +
                                ((chunk ^ ((row >> 1) & 3)) << 4));
                }
                #pragma unroll
                for (int p = 0; p < 4; p++) {
                    int row = warp_n * 64 + p * 16 + rowin;
                    LDMATRIX_X4(rb[p], Bs + row * 64 +
                                ((chunk ^ ((row >> 1) & 3)) << 4));
                }
                #pragma unroll
                for (int jj = 0; jj < 2; jj++) {   // two k16 steps per k32
                    uint32_t af[2][4];
                    #pragma unroll
                    for (int t = 0; t < 2; t++) {
                        cvt_u8(ra[t][2 * jj],     af[t][0], af[t][2]);
                        cvt_u8(ra[t][2 * jj + 1], af[t][1], af[t][3]);
                    }
                    #pragma unroll
                    for (int p = 0; p < 4; p++) {
                        uint32_t b0, b1, b2, b3;
                        cvt_u8(rb[p][2 * jj],     b0, b1);  // n8 low
                        cvt_u8(rb[p][2 * jj + 1], b2, b3);  // n8 high
                        #pragma unroll
                        for (int t = 0; t < 2; t++) {
                            mma_f16(acc[t][2 * p],     af[t], b0, b1);
                            mma_f16(acc[t][2 * p + 1], af[t], b2, b3);
                        }
                    }
                }
            }
        }

        // -------- epilogue: out = acc * xs * sc[n] + bias[n] --------
        const float* sc = reinterpret_cast<const float*>(smem + SOFF_SC);
        const float* bi = reinterpret_cast<const float*>(smem + SOFF_BI);
        int rbase = m0 + warp_m * 32 + (lane >> 2);
        #pragma unroll
        for (int t = 0; t < 2; t++) {
            #pragma unroll
            for (int q = 0; q < 8; q++) {
                int col = warp_n * 64 + q * 8 + (lane & 3) * 2;
                float s0 = xs * sc[col],     s1 = xs * sc[col + 1];
                float b0 = bi[col],          b1 = bi[col + 1];
                int row = rbase + t * 16;
                float2 v0, v1;
                v0.x = acc[t][q][0] * s0 + b0;
                v0.y = acc[t][q][1] * s1 + b1;
                v1.x = acc[t][q][2] * s0 + b0;
                v1.y = acc[t][q][3] * s1 + b1;
                *reinterpret_cast<float2*>(out + (size_t)row * NN + n0 + col) = v0;
                *reinterpret_cast<float2*>(out + (size_t)(row + 8) * NN + n0 + col) = v1;
            }
        }

        // restage sc/bias for next tile
        int nt = mytile + G;
        if (nt < NTILES) {
            __syncthreads();
            int nn0 = (nt % TILES_X) * BN;
            for (int c = tid; c < BN; c += NTHREADS) {
                reinterpret_cast<float*>(smem + SOFF_SC)[c] = wsc[nn0 + c];
                reinterpret_cast<float*>(smem + SOFF_BI)[c] = bias[nn0 + c];
            }
        }
    }
}

// ============================================================
// kernel_launch
// Inputs: x[8192*4096] f32, weight_int8[4096*4096] f32,
//         w_scale[4096] f32, bias[4096] f32, x_scale[1] f32
// Output: f32 [8192*4096]
// ============================================================
extern "C" void kernel_launch(void* const* d_in, const int* in_sizes, int n_in,
                              void* d_out, int out_size) {
    const float* x    = (const float*)d_in[0];
    const float* w    = (const float*)d_in[1];
    const float* wsc  = (const float*)d_in[2];
    const float* bias = (const float*)d_in[3];
    const float* xs   = (const float*)d_in[4];
    float* out = (float*)d_out;

    static int n_sm = 0;
    if (n_sm == 0) {
        cudaDeviceGetAttribute(&n_sm, cudaDevAttrMultiProcessorCount, 0);
        if (n_sm <= 0) n_sm = 148;
        cudaFuncSetAttribute(w8a8_gemm_kernel,
                             cudaFuncAttributeMaxDynamicSharedMemorySize,
                             SMEM_TOTAL);
    }

    // quantize + permute pre-pass (x and w in one launch)
    int n32x = MM * KK / 32;
    int n32w = NN * KK / 32;
    int n32tot = n32x + n32w;
    quantize_kernel<<<(n32tot + 255) / 256, 256>>>(
        (const float4*)x, (const float4*)w, xs, n32x, n32tot);

    // persistent GEMM
    int grid = n_sm < NTILES ? n_sm : NTILES;
    w8a8_gemm_kernel<<<grid, NTHREADS, SMEM_TOTAL>>>(out, wsc, bias, xs);
}

// round 7
// speedup vs baseline: 1.2877x; 1.2877x over previous
#include <cuda_runtime.h>
#include <cuda_bf16.h>
#include <cstdint>

// ============================================================
// W8A8 linear: out[M,N] = xs * (Xq[M,K] @ Wq[N,K]^T) * wsc[n] + bias[n]
//   M = 8192, N = 4096, K = 4096
// Base-sm_103 (compute_103 virtual arch; no tcgen05).
// Round 7: revert to bf16-smem HMMA (round-5 base, best at 650us GEMM),
// then amortize per-kit overhead: BK=128 (256B rows), 2-stage ring,
// 32 k-iterations (half the barriers/waits), loads issued right after
// the barrier so cp.async drains under the 4096-cyc compute slab.
// ============================================================

#define MM 8192
#define NN 4096
#define KK 4096

#define BM 128
#define BN 256
#define BK 128                // bf16 elements; 256 bytes per row
#define STAGES 2
#define KITERS (KK / BK)      // 32
#define NTHREADS 256          // 8 warps
#define TILES_X (NN / BN)     // 16
#define NTILES ((MM / BM) * (NN / BN))   // 1024

// ---- device scratch: quantized bf16 operands ----
__device__ __align__(128) __nv_bfloat16 g_xq[(size_t)MM * KK];
__device__ __align__(128) __nv_bfloat16 g_wq[(size_t)NN * KK];

// ============================================================
// PTX helpers (base-arch only)
// ============================================================
__device__ __forceinline__ uint32_t smem_to_u32(const void* p) {
    uint32_t a;
    asm("{ .reg .u64 t; cvta.to.shared.u64 t, %1; cvt.u32.u64 %0, t; }"
        : "=r"(a) : "l"(p));
    return a;
}

__device__ __forceinline__ void cp_async16(uint32_t dst, const void* src) {
    asm volatile("cp.async.cg.shared.global [%0], [%1], 16;"
                 :: "r"(dst), "l"(src) : "memory");
}
#define CP_COMMIT() asm volatile("cp.async.commit_group;" ::: "memory")
#define CP_WAIT(n)  asm volatile("cp.async.wait_group %0;" :: "n"(n) : "memory")

#define LDMATRIX_X4(r, addr) \
    asm volatile("ldmatrix.sync.aligned.m8n8.x4.shared.b16 {%0,%1,%2,%3}, [%4];" \
                 : "=r"((r)[0]), "=r"((r)[1]), "=r"((r)[2]), "=r"((r)[3]) \
                 : "r"(addr))

// D(16x8 f32) += A(16x16 bf16, row-major) * B(16x8 bf16, col operand)
__device__ __forceinline__ void mma_bf16(float* d, const uint32_t* a,
                                         uint32_t b0, uint32_t b1) {
    asm volatile(
        "mma.sync.aligned.m16n8k16.row.col.f32.bf16.bf16.f32 "
        "{%0,%1,%2,%3}, {%4,%5,%6,%7}, {%8,%9}, {%0,%1,%2,%3};"
        : "+f"(d[0]), "+f"(d[1]), "+f"(d[2]), "+f"(d[3])
        : "r"(a[0]), "r"(a[1]), "r"(a[2]), "r"(a[3]),
          "r"(b0), "r"(b1));
}

// ============================================================
// Fused quantization pre-pass (x -> g_xq scaled; w -> g_wq passthrough)
// ============================================================
__device__ __forceinline__ uint2 quant4_bf16(float4 v, float s) {
    float a = fminf(127.f, fmaxf(-128.f, rintf(v.x / s)));
    float b = fminf(127.f, fmaxf(-128.f, rintf(v.y / s)));
    float c = fminf(127.f, fmaxf(-128.f, rintf(v.z / s)));
    float d = fminf(127.f, fmaxf(-128.f, rintf(v.w / s)));
    __nv_bfloat162 lo = __floats2bfloat162_rn(a, b);
    __nv_bfloat162 hi = __floats2bfloat162_rn(c, d);
    uint2 p;
    p.x = *reinterpret_cast<uint32_t*>(&lo);
    p.y = *reinterpret_cast<uint32_t*>(&hi);
    return p;
}

__global__ void quantize_kernel(const float4* __restrict__ x4,
                                const float4* __restrict__ w4,
                                const float* __restrict__ xs_ptr,
                                int n4x, int n4tot) {
    int i = blockIdx.x * blockDim.x + threadIdx.x;
    if (i >= n4tot) return;
    if (i < n4x) {
        float s = __ldg(xs_ptr);
        reinterpret_cast<uint2*>(g_xq)[i] = quant4_bf16(x4[i], s);
    } else {
        int j = i - n4x;
        float4 v = w4[j];   // already integer-valued
        __nv_bfloat162 lo = __floats2bfloat162_rn(v.x, v.y);
        __nv_bfloat162 hi = __floats2bfloat162_rn(v.z, v.w);
        uint2 p;
        p.x = *reinterpret_cast<uint32_t*>(&lo);
        p.y = *reinterpret_cast<uint32_t*>(&hi);
        reinterpret_cast<uint2*>(g_wq)[j] = p;
    }
}

// ============================================================
// GEMM kernel: persistent CTAs, 2-stage double buffer, BK=128.
//   256 threads = 8 warps, warp grid 2(m) x 4(n), warp tile 64x64.
//   Rows are 256B (two 128B halves); swizzle within each half:
//   off = row*256 + (chunk&8)*16 + (((chunk&7) ^ (row&7)) << 4)
//   -> ldmatrix conflict-free.
// Per kit: wait(0) -> barrier -> issue next kit loads -> compute.
// ============================================================
#define SOFF_SC   0
#define SOFF_BI   1024
#define SOFF_ST   2048
#define ROWB      256                          // bytes per smem row
#define STAGE_BYTES ((BM + BN) * ROWB)         // 98304
#define ASTAGE(s) (SOFF_ST + (s) * STAGE_BYTES)
#define BSTAGE(s) (ASTAGE(s) + BM * ROWB)
#define SMEM_TOTAL (SOFF_ST + STAGES * STAGE_BYTES)   // 198656

__device__ __forceinline__ uint32_t swz(int row, int chunk) {
    return (uint32_t)(row * ROWB + ((chunk & 8) << 4) +
                      (((chunk & 7) ^ (row & 7)) << 4));
}

__device__ __forceinline__ void load_stage(uint32_t sb, int s, int kiter,
                                           int m0, int n0, int tid) {
    int k0 = kiter * BK;
    const __nv_bfloat16* Ab = g_xq + (size_t)m0 * KK + k0;
    const __nv_bfloat16* Bb = g_wq + (size_t)n0 * KK + k0;
    #pragma unroll
    for (int i = 0; i < (BM + BN) * 16 / NTHREADS; i++) {   // 24
        int idx = tid + i * NTHREADS;
        int row = idx >> 4;
        int c = idx & 15;                                   // 16B chunk (8 bf16)
        if (row < BM) {
            cp_async16(sb + ASTAGE(s) + swz(row, c),
                       Ab + (size_t)row * KK + c * 8);
        } else {
            int br = row - BM;
            cp_async16(sb + BSTAGE(s) + swz(br, c),
                       Bb + (size_t)br * KK + c * 8);
        }
    }
}

__global__ void __launch_bounds__(NTHREADS, 1)
w8a8_gemm_kernel(float* __restrict__ out,
                 const float* __restrict__ wsc,
                 const float* __restrict__ bias,
                 const float* __restrict__ xs_ptr) {
    extern __shared__ char smem[];
    uint32_t sb = smem_to_u32(smem);
    int tid  = threadIdx.x;
    int wid  = tid >> 5;
    int lane = tid & 31;
    int warp_m = wid & 1;     // m offset warp_m*64
    int warp_n = wid >> 1;    // n offset warp_n*64
    int G = gridDim.x;

    // ---- load cursor: continuous across this CTA's tile list ----
    int ltile = blockIdx.x;
    int lkit  = 0;
    int ls    = 0;

    // ---- stage sc/bias for first tile ----
    {
        int n0 = (blockIdx.x % TILES_X) * BN;
        for (int c = tid; c < BN; c += NTHREADS) {
            reinterpret_cast<float*>(smem + SOFF_SC)[c] = wsc[n0 + c];
            reinterpret_cast<float*>(smem + SOFF_BI)[c] = bias[n0 + c];
        }
    }

    // prologue: load kit 0 into stage 0
    {
        int lm0 = (ltile / TILES_X) * BM;
        int ln0 = (ltile % TILES_X) * BN;
        load_stage(sb, ls, lkit, lm0, ln0, tid);
        ls ^= 1;
        if (++lkit == KITERS) { lkit = 0; ltile += G; }
        CP_COMMIT();
    }

    float xs = __ldg(xs_ptr);

    // ldmatrix lane address components (validated in rounds 3-5)
    int arow  = lane & 15;                        // A rows within m16
    int ahalf = lane >> 4;                        // A 16B half of k16 (32B)
    int brow  = (lane & 7) + ((lane & 16) >> 1);  // B n-rows (two n8 tiles)
    int bhalf = (lane >> 3) & 1;                  // B 16B half of k16

    int cs = 0;   // compute stage

    for (int mytile = blockIdx.x; mytile < NTILES; mytile += G) {
        int m0 = (mytile / TILES_X) * BM;
        int n0 = (mytile % TILES_X) * BN;

        float acc[4][8][4] = {};   // [m16 tile][n8 tile][frag]

        for (int kit = 0; kit < KITERS; kit++) {
            CP_WAIT(0);           // this kit's data (had a full slab to land)
            __syncthreads();      // everyone done with the other stage

            // issue next kit's loads into the other stage; they drain
            // under the 4096-cycle compute below
            if (ltile < NTILES) {
                int lm0 = (ltile / TILES_X) * BM;
                int ln0 = (ltile % TILES_X) * BN;
                load_stage(sb, ls, lkit, lm0, ln0, tid);
                ls ^= 1;
                if (++lkit == KITERS) { lkit = 0; ltile += G; }
            }
            CP_COMMIT();

            uint32_t As = sb + ASTAGE(cs);
            uint32_t Bs = sb + BSTAGE(cs);
            cs ^= 1;

            #pragma unroll
            for (int j = 0; j < BK / 16; j++) {      // 8 k16 steps
                uint32_t a[4][4];
                #pragma unroll
                for (int t = 0; t < 4; t++) {
                    int row = warp_m * 64 + t * 16 + arow;
                    LDMATRIX_X4(a[t], As + swz(row, j * 2 + ahalf));
                }
                uint32_t b[4][4];
                #pragma unroll
                for (int p = 0; p < 4; p++) {
                    int row = warp_n * 64 + p * 16 + brow;
                    LDMATRIX_X4(b[p], Bs + swz(row, j * 2 + bhalf));
                }
                #pragma unroll
                for (int t = 0; t < 4; t++) {
                    #pragma unroll
                    for (int p = 0; p < 4; p++) {
                        mma_bf16(acc[t][2 * p],     a[t], b[p][0], b[p][1]);
                        mma_bf16(acc[t][2 * p + 1], a[t], b[p][2], b[p][3]);
                    }
                }
            }
        }

        // -------- epilogue: out = acc * xs * sc[n] + bias[n] --------
        // (next tile's kit-0 cp.async already in flight underneath)
        const float* sc = reinterpret_cast<const float*>(smem + SOFF_SC);
        const float* bi = reinterpret_cast<const float*>(smem + SOFF_BI);
        int rbase = m0 + warp_m * 64 + (lane >> 2);
        #pragma unroll
        for (int t = 0; t < 4; t++) {
            #pragma unroll
            for (int q = 0; q < 8; q++) {
                int col = warp_n * 64 + q * 8 + (lane & 3) * 2;
                float s0 = xs * sc[col],     s1 = xs * sc[col + 1];
                float b0 = bi[col],          b1 = bi[col + 1];
                int row = rbase + t * 16;
                float2 v0, v1;
                v0.x = acc[t][q][0] * s0 + b0;
                v0.y = acc[t][q][1] * s1 + b1;
                v1.x = acc[t][q][2] * s0 + b0;
                v1.y = acc[t][q][3] * s1 + b1;
                *reinterpret_cast<float2*>(out + (size_t)row * NN + n0 + col) = v0;
                *reinterpret_cast<float2*>(out + (size_t)(row + 8) * NN + n0 + col) = v1;
            }
        }

        // restage sc/bias for next tile (separate smem region from stages)
        int nt = mytile + G;
        if (nt < NTILES) {
            __syncthreads();   // epilogue reads done before overwrite
            int nn0 = (nt % TILES_X) * BN;
            for (int c = tid; c < BN; c += NTHREADS) {
                reinterpret_cast<float*>(smem + SOFF_SC)[c] = wsc[nn0 + c];
                reinterpret_cast<float*>(smem + SOFF_BI)[c] = bias[nn0 + c];
            }
        }
    }
}

// ============================================================
// kernel_launch
// Inputs: x[8192*4096] f32, weight_int8[4096*4096] f32,
//         w_scale[4096] f32, bias[4096] f32, x_scale[1] f32
// Output: f32 [8192*4096]
// ============================================================
extern "C" void kernel_launch(void* const* d_in, const int* in_sizes, int n_in,
                              void* d_out, int out_size) {
    const float* x    = (const float*)d_in[0];
    const float* w    = (const float*)d_in[1];
    const float* wsc  = (const float*)d_in[2];
    const float* bias = (const float*)d_in[3];
    const float* xs   = (const float*)d_in[4];
    float* out = (float*)d_out;

    static int n_sm = 0;
    if (n_sm == 0) {
        cudaDeviceGetAttribute(&n_sm, cudaDevAttrMultiProcessorCount, 0);
        if (n_sm <= 0) n_sm = 148;
        cudaFuncSetAttribute(w8a8_gemm_kernel,
                             cudaFuncAttributeMaxDynamicSharedMemorySize,
                             SMEM_TOTAL);
    }

    // fused quantize pre-pass
    int n4x = MM * KK / 4;
    int n4w = NN * KK / 4;
    int n4tot = n4x + n4w;
    quantize_kernel<<<(n4tot + 255) / 256, 256>>>(
        (const float4*)x, (const float4*)w, xs, n4x, n4tot);

    // persistent GEMM
    int grid = n_sm < NTILES ? n_sm : NTILES;
    w8a8_gemm_kernel<<<grid, NTHREADS, SMEM_TOTAL>>>(out, wsc, bias, xs);
}